// round 8
// baseline (speedup 1.0000x reference)
#include <cuda_runtime.h>

#define NN 30000
#define NE 480000
#define CH 64
#define NHEADS 4
#define KZ 256          // 64 channels x 4 heads
#define BNGRID 60
#define SCAN_BLOCKS ((NN + 255) / 256)   // 118

typedef unsigned long long ull;

// ---------------- f32x2 helpers (sm_103a packed fp32 pipe) ----------------
__device__ __forceinline__ ull pk2(float lo, float hi) {
    ull r;
    asm("mov.b64 %0, {%1, %2};" : "=l"(r) : "f"(lo), "f"(hi));
    return r;
}
__device__ __forceinline__ void upk2(float& lo, float& hi, ull v) {
    asm("mov.b64 {%0, %1}, %2;" : "=f"(lo), "=f"(hi) : "l"(v));
}
__device__ __forceinline__ ull fma2(ull a, ull b, ull c) {
    ull d;
    asm("fma.rn.f32x2 %0, %1, %2, %3;" : "=l"(d) : "l"(a), "l"(b), "l"(c));
    return d;
}
__device__ __forceinline__ ull mul2(ull a, ull b) {
    ull d;
    asm("mul.rn.f32x2 %0, %1, %2;" : "=l"(d) : "l"(a), "l"(b));
    return d;
}

// ---------------- scratch (device globals; no allocations allowed) ----------------
__device__ __align__(16) float g_L[NN * 4];        // per-node head logits
__device__ __align__(16) float g_attnP[NE * 4];    // per-edge attention, CSR order
__device__ __align__(16) float g_Z[NN * KZ];       // aggregated weighted features [node][c*4+m]
__device__ __align__(16) float g_H[NN * CH];       // relu(conv) output between layers
__device__ __align__(16) float g_Wd[KZ * CH * 2];  // permuted + duplicated weight
__device__ int   g_deg[NN];
__device__ int   g_rowptr[NN + 1];
__device__ int   g_wptr[NN];
__device__ __align__(8) int2 g_sd[NE];             // (src,dst) per CSR position
__device__ int   g_bsum[SCAN_BLOCKS];
__device__ int   g_boff[SCAN_BLOCKS];
__device__ float g_bnp[BNGRID * CH];
__device__ float g_bnp2[BNGRID * CH];
__device__ float g_scale[CH];
__device__ float g_shift[CH];

// ---------------- CSR build ----------------
__global__ void k_count(const int* __restrict__ dstE) {
    int e = blockIdx.x * blockDim.x + threadIdx.x;
    if (e < NE) atomicAdd(&g_deg[dstE[e]], 1);
}

// block-level scan: each block scans 256 degrees, writes local exclusive + block sum
__global__ void k_scan1() {
    int b = blockIdx.x, t = threadIdx.x;
    int i = b * 256 + t;
    int v = (i < NN) ? g_deg[i] : 0;
    int lane = t & 31, wid = t >> 5;
    int x = v;
    #pragma unroll
    for (int off = 1; off < 32; off <<= 1) {
        int y = __shfl_up_sync(0xFFFFFFFFu, x, off);
        if (lane >= off) x += y;
    }
    __shared__ int wsum[8];
    if (lane == 31) wsum[wid] = x;
    __syncthreads();
    if (wid == 0) {
        int s = (lane < 8) ? wsum[lane] : 0;
        #pragma unroll
        for (int off = 1; off < 8; off <<= 1) {
            int y = __shfl_up_sync(0xFFFFFFFFu, s, off);
            if (lane >= off) s += y;
        }
        if (lane < 8) wsum[lane] = s;   // inclusive warp sums
    }
    __syncthreads();
    int base = (wid > 0) ? wsum[wid - 1] : 0;
    int excl = base + x - v;
    if (i < NN) g_rowptr[i] = excl;
    if (t == 255) g_bsum[b] = base + x;
}

// scan the 118 block sums (single small block)
__global__ void k_scan2() {
    int t = threadIdx.x;  // 128 threads
    int v = (t < SCAN_BLOCKS) ? g_bsum[t] : 0;
    int lane = t & 31, wid = t >> 5;
    int x = v;
    #pragma unroll
    for (int off = 1; off < 32; off <<= 1) {
        int y = __shfl_up_sync(0xFFFFFFFFu, x, off);
        if (lane >= off) x += y;
    }
    __shared__ int ws[4];
    if (lane == 31) ws[wid] = x;
    __syncthreads();
    if (t == 0) {
        int a = 0;
        #pragma unroll
        for (int wv = 0; wv < 4; wv++) { int tmp = ws[wv]; ws[wv] = a; a += tmp; }
    }
    __syncthreads();
    int excl = ws[wid] + x - v;
    if (t < SCAN_BLOCKS) g_boff[t] = excl;
    if (t == 0) g_rowptr[NN] = NE;
}

__global__ void k_scan3() {
    int b = blockIdx.x;
    int i = b * 256 + threadIdx.x;
    if (i < NN) {
        int r = g_rowptr[i] + g_boff[b];
        g_rowptr[i] = r;
        g_wptr[i] = r;
    }
}

__global__ void k_scatter(const int* __restrict__ srcE, const int* __restrict__ dstE) {
    int e = blockIdx.x * blockDim.x + threadIdx.x;
    if (e < NE) {
        int s = srcE[e];
        int d = dstE[e];
        int p = atomicAdd(&g_wptr[d], 1);
        g_sd[p] = make_int2(s, d);
    }
}

// ---------------- per-node head logits: L[n][m] = sum_k xhat[n][k] * U[m][k] ----------------
__global__ void k_L(const float* __restrict__ X, const float* __restrict__ U, int use_bn) {
    int w = (blockIdx.x * blockDim.x + threadIdx.x) >> 5;
    int t = threadIdx.x & 31;
    if (w >= NN) return;
    const float* Xp = X ? X : g_H;
    int k0 = 2 * t;
    float sc0 = 1.f, sc1 = 1.f, sh0 = 0.f, sh1 = 0.f;
    if (use_bn) { sc0 = g_scale[k0]; sc1 = g_scale[k0 + 1]; sh0 = g_shift[k0]; sh1 = g_shift[k0 + 1]; }
    float2 xv = *(const float2*)(Xp + (size_t)w * CH + k0);
    float x0 = fmaf(xv.x, sc0, sh0);
    float x1 = fmaf(xv.y, sc1, sh1);
    float p0 = x0 * U[0 * CH + k0] + x1 * U[0 * CH + k0 + 1];
    float p1 = x0 * U[1 * CH + k0] + x1 * U[1 * CH + k0 + 1];
    float p2 = x0 * U[2 * CH + k0] + x1 * U[2 * CH + k0 + 1];
    float p3 = x0 * U[3 * CH + k0] + x1 * U[3 * CH + k0 + 1];
    #pragma unroll
    for (int off = 16; off; off >>= 1) {
        p0 += __shfl_xor_sync(0xFFFFFFFFu, p0, off);
        p1 += __shfl_xor_sync(0xFFFFFFFFu, p1, off);
        p2 += __shfl_xor_sync(0xFFFFFFFFu, p2, off);
        p3 += __shfl_xor_sync(0xFFFFFFFFu, p3, off);
    }
    if (t == 0) {
        *(float4*)(g_L + (size_t)w * 4) = make_float4(p0, p1, p2, p3);
    }
}

// ---------------- per-edge attention in CSR order ----------------
// reads g_sd sequentially; L[dst] is near-broadcast (dst sorted), L[src] gathered.
__global__ void k_attn(const float* __restrict__ cc) {
    int p = blockIdx.x * blockDim.x + threadIdx.x;
    if (p >= NE) return;
    int2 sd = g_sd[p];
    float4 ls = *(const float4*)(g_L + (size_t)sd.x * 4);
    float4 ld = *(const float4*)(g_L + (size_t)sd.y * 4);
    float l0 = ld.x - ls.x + cc[0];
    float l1 = ld.y - ls.y + cc[1];
    float l2 = ld.z - ls.z + cc[2];
    float l3 = ld.w - ls.w + cc[3];
    float mx = fmaxf(fmaxf(l0, l1), fmaxf(l2, l3));
    float e0 = __expf(l0 - mx), e1 = __expf(l1 - mx), e2 = __expf(l2 - mx), e3 = __expf(l3 - mx);
    float inv = __fdividef(1.f, e0 + e1 + e2 + e3);
    *(float4*)(g_attnP + (size_t)p * 4) = make_float4(e0 * inv, e1 * inv, e2 * inv, e3 * inv);
}

// ---------------- warp-per-node aggregation into Z (f32x2, 8x load batching) ----------------
__global__ void k_edge(const float* __restrict__ X, const float* __restrict__ cc, int use_bn) {
    int w = (blockIdx.x * blockDim.x + threadIdx.x) >> 5;
    int t = threadIdx.x & 31;
    if (w >= NN) return;
    const float* Xp = X ? X : g_H;
    int lo = g_rowptr[w], hi = g_rowptr[w + 1];
    float inv = __fdividef(1.f, (float)(hi - lo + 1));
    int k0 = 2 * t;
    float sc0 = 1.f, sc1 = 1.f, sh0 = 0.f, sh1 = 0.f;
    if (use_bn) { sc0 = g_scale[k0]; sc1 = g_scale[k0 + 1]; sh0 = g_shift[k0]; sh1 = g_shift[k0 + 1]; }

    // self-loop attention = softmax(c)
    float c0 = cc[0], c1 = cc[1], c2 = cc[2], c3 = cc[3];
    float mx = fmaxf(fmaxf(c0, c1), fmaxf(c2, c3));
    float e0 = __expf(c0 - mx), e1 = __expf(c1 - mx), e2 = __expf(c2 - mx), e3 = __expf(c3 - mx);
    float si = __fdividef(1.f, e0 + e1 + e2 + e3);
    ull W01 = pk2(e0 * si, e1 * si);
    ull W23 = pk2(e2 * si, e3 * si);

    float2 xv = *(const float2*)(Xp + (size_t)w * CH + k0);
    float xv0 = fmaf(xv.x, sc0, sh0);
    float xv1 = fmaf(xv.y, sc1, sh1);
    ull acc00 = mul2(pk2(xv0, xv0), W01);
    ull acc01 = mul2(pk2(xv0, xv0), W23);
    ull acc10 = mul2(pk2(xv1, xv1), W01);
    ull acc11 = mul2(pk2(xv1, xv1), W23);

    int i = lo;
    for (; i + 8 <= hi; i += 8) {
        int s[8];
        #pragma unroll
        for (int u = 0; u < 8; u++) s[u] = g_sd[i + u].x;
        float2 xs[8];
        #pragma unroll
        for (int u = 0; u < 8; u++) xs[u] = *(const float2*)(Xp + (size_t)s[u] * CH + k0);
        ulonglong2 A[8];
        #pragma unroll
        for (int u = 0; u < 8; u++) A[u] = *(const ulonglong2*)(g_attnP + (size_t)(i + u) * 4);
        #pragma unroll
        for (int u = 0; u < 8; u++) {
            float a = fmaf(xs[u].x, sc0, sh0), b = fmaf(xs[u].y, sc1, sh1);
            ull pa = pk2(a, a), pb = pk2(b, b);
            acc00 = fma2(pa, A[u].x, acc00); acc01 = fma2(pa, A[u].y, acc01);
            acc10 = fma2(pb, A[u].x, acc10); acc11 = fma2(pb, A[u].y, acc11);
        }
    }
    for (; i < hi; i++) {
        int s = g_sd[i].x;
        ulonglong2 A = *(const ulonglong2*)(g_attnP + (size_t)i * 4);
        float2 x = *(const float2*)(Xp + (size_t)s * CH + k0);
        float a = fmaf(x.x, sc0, sh0), b = fmaf(x.y, sc1, sh1);
        ull pa = pk2(a, a), pb = pk2(b, b);
        acc00 = fma2(pa, A.x, acc00); acc01 = fma2(pa, A.y, acc01);
        acc10 = fma2(pb, A.x, acc10); acc11 = fma2(pb, A.y, acc11);
    }

    ull iv = pk2(inv, inv);
    ulonglong2 r0, r1;
    r0.x = mul2(acc00, iv); r0.y = mul2(acc01, iv);
    r1.x = mul2(acc10, iv); r1.y = mul2(acc11, iv);
    float* zr = g_Z + (size_t)w * KZ + k0 * 4;
    *(ulonglong2*)(zr)     = r0;
    *(ulonglong2*)(zr + 4) = r1;
}

// ---------------- permute + duplicate W: Wd[(c*4+m)*128 + 2o + {0,1}] = W[m*64+o][c] ----------------
__global__ void k_permW(const float* __restrict__ W) {
    int idx = blockIdx.x * blockDim.x + threadIdx.x;   // over KZ*CH = 16384
    if (idx >= KZ * CH) return;
    int r = idx >> 6;   // W row = m*64+o
    int c = idx & 63;   // channel
    int m = r >> 6;
    int o = r & 63;
    float v = W[idx];
    int base = (c * 4 + m) * 128 + o * 2;
    g_Wd[base] = v;
    g_Wd[base + 1] = v;
}

// ---------------- dense GEMM with packed f32x2 FMAs (pre-duplicated W) ----------------
__global__ void __launch_bounds__(256) k_gemm(const float* __restrict__ b,
                                              float* __restrict__ extout, int relu) {
    __shared__ __align__(16) float Xs[64 * 132];
    int tid = threadIdx.x;
    int nb = blockIdx.x * 128;
    float* out = extout ? extout : g_H;

    ull acc[4][4];  // [node pair][col]
    #pragma unroll
    for (int p = 0; p < 4; p++)
        #pragma unroll
        for (int j = 0; j < 4; j++) acc[p][j] = 0ull;

    int tx = tid & 15;      // col group (4 cols)
    int ty = tid >> 4;      // node group (8 nodes)

    for (int kc = 0; kc < 4; kc++) {
        // stage 64 k-rows x 128 nodes of Z, transposed
        #pragma unroll
        for (int i = 0; i < 8; i++) {
            int f = i * 256 + tid;
            int nl = f >> 4;
            int kl = (f & 15) << 2;
            int node = nb + nl;
            float4 z = make_float4(0.f, 0.f, 0.f, 0.f);
            if (node < NN) z = *(const float4*)(g_Z + (size_t)node * KZ + kc * 64 + kl);
            Xs[(kl + 0) * 132 + nl] = z.x;
            Xs[(kl + 1) * 132 + nl] = z.y;
            Xs[(kl + 2) * 132 + nl] = z.z;
            Xs[(kl + 3) * 132 + nl] = z.w;
        }
        __syncthreads();
        #pragma unroll 8
        for (int kk = 0; kk < 64; kk++) {
            const float* xr = Xs + kk * 132 + ty * 8;
            ulonglong2 xa = *(const ulonglong2*)xr;         // node pairs (0,1),(2,3)
            ulonglong2 xb = *(const ulonglong2*)(xr + 4);   // node pairs (4,5),(6,7)
            const float* wr = g_Wd + (size_t)(kc * 64 + kk) * 128 + tx * 8;
            ulonglong2 wA = *(const ulonglong2*)wr;         // w0dup, w1dup
            ulonglong2 wB = *(const ulonglong2*)(wr + 4);   // w2dup, w3dup
            acc[0][0] = fma2(xa.x, wA.x, acc[0][0]); acc[0][1] = fma2(xa.x, wA.y, acc[0][1]);
            acc[0][2] = fma2(xa.x, wB.x, acc[0][2]); acc[0][3] = fma2(xa.x, wB.y, acc[0][3]);
            acc[1][0] = fma2(xa.y, wA.x, acc[1][0]); acc[1][1] = fma2(xa.y, wA.y, acc[1][1]);
            acc[1][2] = fma2(xa.y, wB.x, acc[1][2]); acc[1][3] = fma2(xa.y, wB.y, acc[1][3]);
            acc[2][0] = fma2(xb.x, wA.x, acc[2][0]); acc[2][1] = fma2(xb.x, wA.y, acc[2][1]);
            acc[2][2] = fma2(xb.x, wB.x, acc[2][2]); acc[2][3] = fma2(xb.x, wB.y, acc[2][3]);
            acc[3][0] = fma2(xb.y, wA.x, acc[3][0]); acc[3][1] = fma2(xb.y, wA.y, acc[3][1]);
            acc[3][2] = fma2(xb.y, wB.x, acc[3][2]); acc[3][3] = fma2(xb.y, wB.y, acc[3][3]);
        }
        __syncthreads();
    }

    float4 bv = *(const float4*)(b + tx * 4);
    #pragma unroll
    for (int p = 0; p < 4; p++) {
        float lo0, hi0, lo1, hi1, lo2, hi2, lo3, hi3;
        upk2(lo0, hi0, acc[p][0]);
        upk2(lo1, hi1, acc[p][1]);
        upk2(lo2, hi2, acc[p][2]);
        upk2(lo3, hi3, acc[p][3]);
        int n0 = nb + ty * 8 + 2 * p;
        if (n0 < NN) {
            float4 r = make_float4(lo0 + bv.x, lo1 + bv.y, lo2 + bv.z, lo3 + bv.w);
            if (relu) {
                r.x = fmaxf(r.x, 0.f); r.y = fmaxf(r.y, 0.f);
                r.z = fmaxf(r.z, 0.f); r.w = fmaxf(r.w, 0.f);
            }
            *(float4*)(out + (size_t)n0 * CH + tx * 4) = r;
        }
        int n1 = n0 + 1;
        if (n1 < NN) {
            float4 r = make_float4(hi0 + bv.x, hi1 + bv.y, hi2 + bv.z, hi3 + bv.w);
            if (relu) {
                r.x = fmaxf(r.x, 0.f); r.y = fmaxf(r.y, 0.f);
                r.z = fmaxf(r.z, 0.f); r.w = fmaxf(r.w, 0.f);
            }
            *(float4*)(out + (size_t)n1 * CH + tx * 4) = r;
        }
    }
}

// ---------------- batch-norm statistics (two-stage, deterministic) ----------------
__global__ void k_bnstat() {
    int ch = threadIdx.x & 63;
    int rg = threadIdx.x >> 6;   // 0..3
    float s = 0.f, s2 = 0.f;
    for (int v = blockIdx.x * 4 + rg; v < NN; v += BNGRID * 4) {
        float val = g_H[(size_t)v * CH + ch];
        s += val;
        s2 += val * val;
    }
    __shared__ float sh[4][64], sh2[4][64];
    sh[rg][ch] = s; sh2[rg][ch] = s2;
    __syncthreads();
    if (rg == 0) {
        s  = sh[0][ch]  + sh[1][ch]  + sh[2][ch]  + sh[3][ch];
        s2 = sh2[0][ch] + sh2[1][ch] + sh2[2][ch] + sh2[3][ch];
        g_bnp[blockIdx.x * 64 + ch]  = s;
        g_bnp2[blockIdx.x * 64 + ch] = s2;
    }
}

__global__ void k_bnfinal(const float* __restrict__ g, const float* __restrict__ bt) {
    int ch = threadIdx.x;
    if (ch >= CH) return;
    float s = 0.f, s2 = 0.f;
    for (int bidx = 0; bidx < BNGRID; bidx++) {
        s  += g_bnp[bidx * 64 + ch];
        s2 += g_bnp2[bidx * 64 + ch];
    }
    float mu = s / (float)NN;
    float var = s2 / (float)NN - mu * mu;
    float sc = g[ch] * rsqrtf(var + 1e-5f);
    g_scale[ch] = sc;
    g_shift[ch] = bt[ch] - mu * sc;
}

// ---------------- launch ----------------
extern "C" void kernel_launch(void* const* d_in, const int* in_sizes, int n_in,
                              void* d_out, int out_size) {
    const float* x    = (const float*)d_in[0];
    const int*   ei   = (const int*)d_in[1];      // edge_index: int32
    const float* W0   = (const float*)d_in[2];
    const float* U0   = (const float*)d_in[3];
    const float* c0   = (const float*)d_in[4];
    const float* b0   = (const float*)d_in[5];
    const float* g0   = (const float*)d_in[6];
    const float* bt0  = (const float*)d_in[7];
    const float* W1   = (const float*)d_in[8];
    const float* U1   = (const float*)d_in[9];
    const float* c1   = (const float*)d_in[10];
    const float* b1   = (const float*)d_in[11];
    const float* g1   = (const float*)d_in[12];
    const float* bt1  = (const float*)d_in[13];
    const float* W2   = (const float*)d_in[14];
    const float* U2   = (const float*)d_in[15];
    const float* c2   = (const float*)d_in[16];
    const float* b2   = (const float*)d_in[17];
    const int* srcE = ei;
    const int* dstE = ei + NE;
    float* out = (float*)d_out;

    const int GB_E = (NE + 255) / 256;      // 1875
    const int GB_N = SCAN_BLOCKS;           // 118
    const int GB_W = NN / 8;                // 3750 (warp per node, exact)
    const int GB_G = (NN + 127) / 128;      // 235
    const int GB_P = (KZ * CH + 255) / 256; // 64

    // CSR build (graph fixed across layers)
    void* degPtr = nullptr;
    cudaGetSymbolAddress(&degPtr, g_deg);
    cudaMemsetAsync(degPtr, 0, NN * sizeof(int));
    k_count<<<GB_E, 256>>>(dstE);
    k_scan1<<<GB_N, 256>>>();
    k_scan2<<<1, 128>>>();
    k_scan3<<<GB_N, 256>>>();
    k_scatter<<<GB_E, 256>>>(srcE, dstE);

    // ---- layer 0 (input x, no BN folding) ----
    k_L<<<GB_W, 256>>>(x, U0, 0);
    k_attn<<<GB_E, 256>>>(c0);
    k_edge<<<GB_W, 256>>>(x, c0, 0);
    k_permW<<<GB_P, 256>>>(W0);
    k_gemm<<<GB_G, 256>>>(b0, nullptr, 1);    // -> g_H (relu'd)
    k_bnstat<<<BNGRID, 256>>>();
    k_bnfinal<<<1, 64>>>(g0, bt0);

    // ---- layer 1 (reads BN0(g_H) on the fly) ----
    k_L<<<GB_W, 256>>>(nullptr, U1, 1);
    k_attn<<<GB_E, 256>>>(c1);
    k_edge<<<GB_W, 256>>>(nullptr, c1, 1);
    k_permW<<<GB_P, 256>>>(W1);
    k_gemm<<<GB_G, 256>>>(b1, nullptr, 1);    // -> g_H (relu'd)
    k_bnstat<<<BNGRID, 256>>>();
    k_bnfinal<<<1, 64>>>(g1, bt1);

    // ---- layer 2 (reads BN1(g_H), no relu, writes d_out) ----
    k_L<<<GB_W, 256>>>(nullptr, U2, 1);
    k_attn<<<GB_E, 256>>>(c2);
    k_edge<<<GB_W, 256>>>(nullptr, c2, 1);
    k_permW<<<GB_P, 256>>>(W2);
    k_gemm<<<GB_G, 256>>>(b2, out, 0);

    (void)in_sizes; (void)n_in; (void)out_size;
}